// round 16
// baseline (speedup 1.0000x reference)
#include <cuda_runtime.h>
#include <cuda_bf16.h>

#define S 512
#define BB 512
#define T 64

__device__ float g_den[BB];
__device__ float g_num[BB];
__device__ unsigned g_tick = 0;   // wraps via atomicInc; never reset

typedef unsigned long long u64;

__device__ __forceinline__ u64 ffma2(u64 a, u64 b, u64 c) {
    u64 d; asm("fma.rn.f32x2 %0, %1, %2, %3;" : "=l"(d) : "l"(a), "l"(b), "l"(c)); return d;
}
__device__ __forceinline__ u64 fadd2(u64 a, u64 b) {
    u64 d; asm("add.rn.f32x2 %0, %1, %2;" : "=l"(d) : "l"(a), "l"(b)); return d;
}
__device__ __forceinline__ u64 pack2(float x, float y) {
    u64 d; asm("mov.b64 %0, {%1, %2};" : "=l"(d) : "f"(x), "f"(y)); return d;
}
__device__ __forceinline__ float2 unpack2(u64 v) {
    float2 r; asm("mov.b64 {%0, %1}, %2;" : "=f"(r.x), "=f"(r.y) : "l"(v)); return r;
}
__device__ __forceinline__ float wsum(float v) {
#pragma unroll
    for (int o = 16; o; o >>= 1) v += __shfl_xor_sync(0xffffffffu, v, o);
    return v;
}
#define PAIR_BAR(id) asm volatile("bar.sync %0, 64;" :: "r"(id) : "memory")

// ---------------------------------------------------------------------------
// R12 skeleton + intra-warp ILP: each pair (2 warps) advances TWO batches.
// The E-register file (64 regs) is shared by both scans; per step a warp
// runs two independent matvec+apply streams (32 LDS.128 + 64 FFMA2) and the
// pair meets at ONE bar. Chain stalls of batch A are filled by batch B's
// instructions inside the same warp.
// grid=128 x block=128 (2 pairs/block): 512 warps, 1 per SMSP on 128 SMs.
// ---------------------------------------------------------------------------
__global__ void __launch_bounds__(128, 2) crf_fused(
    const float* __restrict__ em,
    const int*   __restrict__ tags,     // int64 downgraded to int32 by harness
    const int*   __restrict__ mask,     // bool widened to int32 by harness
    const float* __restrict__ trans,
    const float* __restrict__ startT,
    const float* __restrict__ endT,
    float* __restrict__ out)
{
    __shared__ __align__(16) float ubuf[2][2][2][T]; // [pair][batch][buf][state]
    __shared__ float spart[2][2][2];                 // [pair][batch][half]
    __shared__ double dpart[4];
    __shared__ unsigned is_last;

    const int warp = threadIdx.x >> 5;   // 0..3
    const int pair = warp >> 1;
    const int half = warp & 1;
    const int j    = threadIdx.x & 31;
    const int o    = half * 32 + j;      // owned output state
    const int bid  = pair + 1;           // named barrier id
    const int b0   = (blockIdx.x * 2 + pair) * 2;   // batches b0, b0+1
    const int b1   = b0 + 1;

    // E column for state o over from-state pairs (shared by both batches)
    u64 Ecol2[T / 2];
#pragma unroll
    for (int p = 0; p < T / 2; p++) {
        Ecol2[p] = pack2(__expf(trans[(2 * p) * T + o]),
                         __expf(trans[(2 * p + 1) * T + o]));
    }

    const size_t stride = (size_t)BB * T;
    const size_t bT0 = (size_t)b0 * T;
    const size_t bT1 = (size_t)b1 * T;

    // ---- init (s = 0) ----
    float uA = __expf(startT[o] + em[bT0 + o]);
    float uB = __expf(startT[o] + em[bT1 + o]);
    int buf = 0;
    ubuf[pair][0][0][o] = uA;
    ubuf[pair][1][0][o] = uB;
    float pwA = wsum(uA);
    float pwB = wsum(uB);
    if (j == 0) { spart[pair][0][half] = pwA; spart[pair][1][half] = pwB; }
    PAIR_BAR(bid);

    float UA0 = spart[pair][0][0] + spart[pair][0][1];
    float UB0 = spart[pair][1][0] + spart[pair][1][1];
    float scaleA = __fdividef(1.0f, UA0), scaleB = __fdividef(1.0f, UB0);
    float pendA  = __logf(UA0),           pendB  = __logf(UB0);
    float KA = 0.0f, KB = 0.0f;

    // chunk prefetch (steps 1..8)
    float xrA[8], xrB[8]; int mrA[8], mrB[8];
#pragma unroll
    for (int q = 0; q < 8; q++) {
        int s = 1 + q;
        xrA[q] = em[stride * s + bT0 + o];
        xrB[q] = em[stride * s + bT1 + o];
        mrA[q] = mask[s * BB + b0];
        mrB[q] = mask[s * BB + b1];
    }

    // dual matvec: two independent FFMA streams sharing the E registers
    auto matvec2 = [&](float& tA, float& tB) {
        const ulonglong2* upA = reinterpret_cast<const ulonglong2*>(ubuf[pair][0][buf]);
        const ulonglong2* upB = reinterpret_cast<const ulonglong2*>(ubuf[pair][1][buf]);
        u64 a0 = 0, a1 = 0, a2 = 0, a3 = 0;
        u64 c0 = 0, c1 = 0, c2 = 0, c3 = 0;
#pragma unroll
        for (int k = 0; k < 8; k++) {
            ulonglong2 vA0 = upA[2 * k];
            ulonglong2 vB0 = upB[2 * k];
            ulonglong2 vA1 = upA[2 * k + 1];
            ulonglong2 vB1 = upB[2 * k + 1];
            a0 = ffma2(vA0.x, Ecol2[4 * k],     a0);
            c0 = ffma2(vB0.x, Ecol2[4 * k],     c0);
            a1 = ffma2(vA0.y, Ecol2[4 * k + 1], a1);
            c1 = ffma2(vB0.y, Ecol2[4 * k + 1], c1);
            a2 = ffma2(vA1.x, Ecol2[4 * k + 2], a2);
            c2 = ffma2(vB1.x, Ecol2[4 * k + 2], c2);
            a3 = ffma2(vA1.y, Ecol2[4 * k + 3], a3);
            c3 = ffma2(vB1.y, Ecol2[4 * k + 3], c3);
        }
        float2 ta = unpack2(fadd2(fadd2(a0, a1), fadd2(a2, a3)));
        float2 tb = unpack2(fadd2(fadd2(c0, c1), fadd2(c2, c3)));
        tA = ta.x + ta.y;
        tB = tb.x + tb.y;
    };

    auto step = [&](float xeA, float xeB, int mA, int mB, int q, bool renorm_chunk) {
        float tA, tB;
        matvec2(tA, tB);
        if (q == 0) {                      // chunk start: apply pending renorm
            float nA = tA * (xeA * scaleA);
            float nB = tB * (xeB * scaleB);
            uA = mA ? nA : uA;             uB = mB ? nB : uB;
            KA += mA ? pendA : 0.0f;       KB += mB ? pendB : 0.0f;
            pendA  = mA ? 0.0f : pendA;    pendB  = mB ? 0.0f : pendB;
            scaleA = mA ? 1.0f : scaleA;   scaleB = mB ? 1.0f : scaleB;
        } else {
            float nA = tA * xeA;
            float nB = tB * xeB;
            uA = mA ? nA : uA;
            uB = mB ? nB : uB;
        }
        buf ^= 1;
        ubuf[pair][0][buf][o] = uA;
        ubuf[pair][1][buf][o] = uB;
        if (q == 6 && renorm_chunk) {      // publish U from step-7's u
            float wA = wsum(uA);           // two independent shfl chains
            float wB = wsum(uB);
            if (j == 0) { spart[pair][0][half] = wA; spart[pair][1][half] = wB; }
        }
        PAIR_BAR(bid);
        if (q == 7 && renorm_chunk) {      // consume after step-8's bar
            float UA = spart[pair][0][0] + spart[pair][0][1];
            float UB = spart[pair][1][0] + spart[pair][1][1];
            scaleA *= __fdividef(1.0f, UA);
            scaleB *= __fdividef(1.0f, UB);
            pendA  += __logf(UA);
            pendB  += __logf(UB);
        }
    };

    for (int c = 0; c < 64; c++) {
        float xeA[8], xeB[8]; int mmA[8], mmB[8];
#pragma unroll
        for (int q = 0; q < 8; q++) {
            xeA[q] = __expf(xrA[q]); xeB[q] = __expf(xrB[q]);
            mmA[q] = mrA[q];         mmB[q] = mrB[q];
        }
        // burst-prefetch next chunk (fire-and-forget, overlaps 8 steps)
#pragma unroll
        for (int q = 0; q < 8; q++) {
            int s = 9 + 8 * c + q;
            s = (s < S) ? s : (S - 1);
            xrA[q] = em[stride * s + bT0 + o];
            xrB[q] = em[stride * s + bT1 + o];
            mrA[q] = mask[s * BB + b0];
            mrB[q] = mask[s * BB + b1];
        }
        if (c < 63) {
#pragma unroll
            for (int q = 0; q < 8; q++) step(xeA[q], xeB[q], mmA[q], mmB[q], q, true);
        } else {
#pragma unroll
            for (int q = 0; q < 7; q++) step(xeA[q], xeB[q], mmA[q], mmB[q], q, false);
        }
    }

    // den = K + pend + log( sum(scale * u * exp(end)) )  for both batches
    {
        float ee = __expf(endT[o]);
        float vA = scaleA * uA * ee;
        float vB = scaleB * uB * ee;
        float wA = wsum(vA);
        float wB = wsum(vB);
        if (j == 0) { spart[pair][0][half] = wA; spart[pair][1][half] = wB; }
        PAIR_BAR(bid);
        if (half == 0 && j == 0) {
            float VA = spart[pair][0][0] + spart[pair][0][1];
            float VB = spart[pair][1][0] + spart[pair][1][1];
            g_den[b0] = KA + pendA + __logf(VA);
            g_den[b1] = KB + pendB + __logf(VB);
        }
    }

    // ---- numerator: warp half handles batch (b0 if half==0 else b1) ----
    {
        const int bn = (half == 0) ? b0 : b1;
        const size_t bTn = (size_t)bn * T;
        int tg[17]; int mk[16];
#pragma unroll
        for (int q = 0; q < 17; q++) {
            int s = 16 * j + q - 1;
            tg[q] = (s >= 0) ? (tags[s * BB + bn] & (T - 1)) : 0;
        }
#pragma unroll
        for (int q = 0; q < 16; q++) mk[q] = mask[(16 * j + q) * BB + bn];

        float acc = 0.0f;
        int cnt = 0;
#pragma unroll
        for (int q = 0; q < 16; q++) {
            int s = 16 * j + q;
            int t = tg[q + 1];
            cnt += (mk[q] ? 1 : 0);
            float e = em[stride * s + bTn + t];
            if (s == 0)       acc += startT[t] + e;
            else if (mk[q])   acc += trans[tg[q] * T + t] + e;
        }
        acc = wsum(acc);
#pragma unroll
        for (int ofs = 16; ofs; ofs >>= 1) cnt += __shfl_xor_sync(0xffffffffu, cnt, ofs);
        if (j == 0) {
            int last = (cnt >= 1) ? (cnt - 1) : 0;
            int lt = tags[last * BB + bn] & (T - 1);
            g_num[bn] = acc + endT[lt];
        }
    }

    // ---- ticket-elected last block computes the mean ----
    __threadfence();
    __syncthreads();
    if (threadIdx.x == 0) {
        unsigned old;
        asm volatile("atom.global.inc.u32 %0, [%1], %2;"
                     : "=r"(old) : "l"(&g_tick), "r"((unsigned)(gridDim.x - 1))
                     : "memory");
        is_last = (old == gridDim.x - 1) ? 1u : 0u;
    }
    __syncthreads();
    if (is_last) {
        int t = threadIdx.x;
        double v = 0.0;
#pragma unroll
        for (int k = 0; k < 4; k++) {
            int idx = t * 4 + k;
            v += (double)g_num[idx] - (double)g_den[idx];
        }
#pragma unroll
        for (int ofs = 16; ofs; ofs >>= 1) v += __shfl_xor_sync(0xffffffffu, v, ofs);
        if (j == 0) dpart[warp] = v;
        __syncthreads();
        if (t == 0) {
            double tot = dpart[0] + dpart[1] + dpart[2] + dpart[3];
            out[0] = (float)(tot * (1.0 / (double)BB));
        }
    }
}

// ---------------------------------------------------------------------------
extern "C" void kernel_launch(void* const* d_in, const int* in_sizes, int n_in,
                              void* d_out, int out_size)
{
    const float* em     = (const float*)d_in[0];
    const int*   tags   = (const int*)d_in[1];
    const int*   mask   = (const int*)d_in[2];
    const float* startT = (const float*)d_in[3];
    const float* endT   = (const float*)d_in[4];
    const float* trans  = (const float*)d_in[5];

    crf_fused<<<BB / 4, 128>>>(em, tags, mask, trans, startT, endT, (float*)d_out);
}

// round 17
// speedup vs baseline: 1.1330x; 1.1330x over previous
#include <cuda_runtime.h>
#include <cuda_bf16.h>

#define S 512
#define BB 512
#define T 64

__device__ float g_den[BB];
__device__ float g_num[BB];
__device__ unsigned g_tick = 0;   // wraps via atomicInc; never reset

typedef unsigned long long u64;

__device__ __forceinline__ u64 ffma2(u64 a, u64 b, u64 c) {
    u64 d; asm("fma.rn.f32x2 %0, %1, %2, %3;" : "=l"(d) : "l"(a), "l"(b), "l"(c)); return d;
}
__device__ __forceinline__ u64 fadd2(u64 a, u64 b) {
    u64 d; asm("add.rn.f32x2 %0, %1, %2;" : "=l"(d) : "l"(a), "l"(b)); return d;
}
__device__ __forceinline__ u64 pack2(float x, float y) {
    u64 d; asm("mov.b64 %0, {%1, %2};" : "=l"(d) : "f"(x), "f"(y)); return d;
}
__device__ __forceinline__ float2 unpack2(u64 v) {
    float2 r; asm("mov.b64 {%0, %1}, %2;" : "=f"(r.x), "=f"(r.y) : "l"(v)); return r;
}
__device__ __forceinline__ float wsum(float v) {
#pragma unroll
    for (int o = 16; o; o >>= 1) v += __shfl_xor_sync(0xffffffffu, v, o);
    return v;
}
#define PAIR_BAR(id) asm volatile("bar.sync %0, 64;" :: "r"(id) : "memory")

// ---------------------------------------------------------------------------
// R12 microstructure, ONE-WAVE packing: block = 256 threads = 4 pairs =
// 4 batches -> grid = 128 blocks <= 148 SMs (no wave quantization).
// Each pair (2 warps) scans one batch; warp owns 32 output states (lane owns
// one). alpha_j = K + log(u_j); scale bookkeeping at chunk starts only;
// renorm published from step-7's u, consumed after step-8's bar.
// Each SMSP hosts 2 warps from DIFFERENT pairs -> stalls interleave.
// ---------------------------------------------------------------------------
__global__ void __launch_bounds__(256, 1) crf_fused(
    const float* __restrict__ em,
    const int*   __restrict__ tags,     // int64 downgraded to int32 by harness
    const int*   __restrict__ mask,     // bool widened to int32 by harness
    const float* __restrict__ trans,
    const float* __restrict__ startT,
    const float* __restrict__ endT,
    float* __restrict__ out)
{
    __shared__ __align__(16) float ubuf[4][2][T];   // [pair][buf][state]
    __shared__ float spart[4][2];                   // [pair][half]
    __shared__ double dpart[8];
    __shared__ unsigned is_last;

    const int warp = threadIdx.x >> 5;   // 0..7
    const int pair = warp >> 1;          // 0..3
    const int half = warp & 1;
    const int j    = threadIdx.x & 31;
    const int o    = half * 32 + j;      // owned output state
    const int bid  = pair + 1;           // named barrier id 1..4
    const int b    = blockIdx.x * 4 + pair;

    // E column for state o over from-state pairs
    u64 Ecol2[T / 2];
#pragma unroll
    for (int p = 0; p < T / 2; p++) {
        Ecol2[p] = pack2(__expf(trans[(2 * p) * T + o]),
                         __expf(trans[(2 * p + 1) * T + o]));
    }

    const size_t bT     = (size_t)b * T;
    const size_t stride = (size_t)BB * T;

    // ---- init (s = 0) ----
    float u = __expf(startT[o] + em[bT + o]);
    int buf = 0;
    ubuf[pair][0][o] = u;
    float pw = wsum(u);
    if (j == 0) spart[pair][half] = pw;
    PAIR_BAR(bid);

    float U0    = spart[pair][0] + spart[pair][1];
    float scale = __fdividef(1.0f, U0);   // pending, applied at chunk start
    float pend  = __logf(U0);
    float K     = 0.0f;

    // prefetch chunk 0 (steps 1..8)
    float xr[8]; int mr[8];
#pragma unroll
    for (int q = 0; q < 8; q++) {
        int s = 1 + q;
        xr[q] = em[stride * s + bT + o];
        mr[q] = mask[s * BB + b];
    }

    // 4-accumulator matvec over the current buffer
    auto matvec = [&]() -> float {
        const ulonglong2* up = reinterpret_cast<const ulonglong2*>(ubuf[pair][buf]);
        u64 a0 = 0, a1 = 0, a2 = 0, a3 = 0;
#pragma unroll
        for (int k = 0; k < 8; k++) {
            ulonglong2 v = up[2 * k];
            ulonglong2 w = up[2 * k + 1];
            a0 = ffma2(v.x, Ecol2[4 * k],     a0);
            a1 = ffma2(v.y, Ecol2[4 * k + 1], a1);
            a2 = ffma2(w.x, Ecol2[4 * k + 2], a2);
            a3 = ffma2(w.y, Ecol2[4 * k + 3], a3);
        }
        float2 tt = unpack2(fadd2(fadd2(a0, a1), fadd2(a2, a3)));
        return tt.x + tt.y;
    };

    auto step = [&](float xe, int m, int q, bool renorm_chunk) {
        float t = matvec();
        float n;
        if (q == 0) {                      // chunk start: apply pending renorm
            n = t * (xe * scale);
            u     = m ? n : u;
            K    += m ? pend : 0.0f;
            pend  = m ? 0.0f : pend;
            scale = m ? 1.0f : scale;
        } else {
            n = t * xe;
            u = m ? n : u;
        }
        buf ^= 1;
        ubuf[pair][buf][o] = u;
        if (q == 6 && renorm_chunk) {      // publish U from step-7's u
            float w = wsum(u);
            if (j == 0) spart[pair][half] = w;
        }
        PAIR_BAR(bid);
        if (q == 7 && renorm_chunk) {      // consume after step-8's bar
            float U = spart[pair][0] + spart[pair][1];
            scale *= __fdividef(1.0f, U);
            pend  += __logf(U);
        }
    };

    for (int c = 0; c < 64; c++) {
        float xe[8]; int mm[8];
#pragma unroll
        for (int q = 0; q < 8; q++) { xe[q] = __expf(xr[q]); mm[q] = mr[q]; }
        // burst-prefetch next chunk (fire-and-forget, overlaps 8 steps)
#pragma unroll
        for (int q = 0; q < 8; q++) {
            int s = 9 + 8 * c + q;
            s = (s < S) ? s : (S - 1);
            xr[q] = em[stride * s + bT + o];
            mr[q] = mask[s * BB + b];
        }
        if (c < 63) {
#pragma unroll
            for (int q = 0; q < 8; q++) step(xe[q], mm[q], q, true);
        } else {
#pragma unroll
            for (int q = 0; q < 7; q++) step(xe[q], mm[q], q, false);
        }
    }

    // den = K + pend + log( sum(scale * u * exp(end)) )
    {
        float v = scale * u * __expf(endT[o]);
        float w = wsum(v);
        if (j == 0) spart[pair][half] = w;
        PAIR_BAR(bid);
        if (o == 0) {
            float V = spart[pair][0] + spart[pair][1];
            g_den[b] = K + pend + __logf(V);
        }
    }

    // ---- numerator (warp half==0 of each pair; lane j owns steps 16j..16j+15)
    if (half == 0) {
        int tg[17]; int mk[16];
#pragma unroll
        for (int q = 0; q < 17; q++) {
            int s = 16 * j + q - 1;
            tg[q] = (s >= 0) ? (tags[s * BB + b] & (T - 1)) : 0;
        }
#pragma unroll
        for (int q = 0; q < 16; q++) mk[q] = mask[(16 * j + q) * BB + b];

        float acc = 0.0f;
        int cnt = 0;
#pragma unroll
        for (int q = 0; q < 16; q++) {
            int s = 16 * j + q;
            int t = tg[q + 1];
            cnt += (mk[q] ? 1 : 0);
            float e = em[stride * s + bT + t];
            if (s == 0)       acc += startT[t] + e;
            else if (mk[q])   acc += trans[tg[q] * T + t] + e;
        }
        acc = wsum(acc);
#pragma unroll
        for (int ofs = 16; ofs; ofs >>= 1) cnt += __shfl_xor_sync(0xffffffffu, cnt, ofs);
        if (j == 0) {
            int last = (cnt >= 1) ? (cnt - 1) : 0;
            int lt = tags[last * BB + b] & (T - 1);
            g_num[b] = acc + endT[lt];
        }
    }

    // ---- ticket-elected last block computes the mean ----
    __threadfence();
    __syncthreads();
    if (threadIdx.x == 0) {
        unsigned old;
        asm volatile("atom.global.inc.u32 %0, [%1], %2;"
                     : "=r"(old) : "l"(&g_tick), "r"((unsigned)(gridDim.x - 1))
                     : "memory");
        is_last = (old == gridDim.x - 1) ? 1u : 0u;
    }
    __syncthreads();
    if (is_last) {
        int t = threadIdx.x;                 // 256 threads, 2 entries each
        double v = 0.0;
#pragma unroll
        for (int k = 0; k < 2; k++) {
            int idx = t * 2 + k;
            v += (double)g_num[idx] - (double)g_den[idx];
        }
#pragma unroll
        for (int ofs = 16; ofs; ofs >>= 1) v += __shfl_xor_sync(0xffffffffu, v, ofs);
        if (j == 0) dpart[warp] = v;
        __syncthreads();
        if (t == 0) {
            double tot = 0.0;
#pragma unroll
            for (int k = 0; k < 8; k++) tot += dpart[k];
            out[0] = (float)(tot * (1.0 / (double)BB));
        }
    }
}

// ---------------------------------------------------------------------------
extern "C" void kernel_launch(void* const* d_in, const int* in_sizes, int n_in,
                              void* d_out, int out_size)
{
    const float* em     = (const float*)d_in[0];
    const int*   tags   = (const int*)d_in[1];
    const int*   mask   = (const int*)d_in[2];
    const float* startT = (const float*)d_in[3];
    const float* endT   = (const float*)d_in[4];
    const float* trans  = (const float*)d_in[5];

    crf_fused<<<BB / 4, 256>>>(em, tags, mask, trans, startT, endT, (float*)d_out);
}